// round 10
// baseline (speedup 1.0000x reference)
#include <cuda_runtime.h>
#include <cstdint>

#define BATCH 8
#define NPTS  8192
#define NGRP  512
#define KNN   32
#define NEIGH_ATTR_OFF 393216   /* 8*512*32*3 */
#define CENTER_OFF     786432
#define CATTR_OFF      798720
#define CAP 1024

#define CSZ   4                 /* cluster CTAs per batch */
#define PPC   2048              /* points per CTA */
#define TAGM  0x7FFFFu

__device__ float  g_center[BATCH * NGRP * 3];
__device__ float4 g_pts[BATCH * NPTS];   // {x, y, z, (x*x+y*y)+z*z}

// ---- packed f32x2 helpers (IEEE rn per lane == scalar FADD/FMUL bitwise) ----
__device__ __forceinline__ unsigned long long f2pack(float lo, float hi) {
    unsigned long long r;
    asm("mov.b64 %0, {%1,%2};" : "=l"(r) : "f"(lo), "f"(hi));
    return r;
}
__device__ __forceinline__ void f2unpack(unsigned long long v, float& lo, float& hi) {
    asm("mov.b64 {%0,%1}, %2;" : "=f"(lo), "=f"(hi) : "l"(v));
}
__device__ __forceinline__ unsigned long long f2add(unsigned long long a, unsigned long long b) {
    unsigned long long r;
    asm("add.rn.f32x2 %0, %1, %2;" : "=l"(r) : "l"(a), "l"(b));
    return r;
}
__device__ __forceinline__ unsigned long long f2mul(unsigned long long a, unsigned long long b) {
    unsigned long long r;
    asm("mul.rn.f32x2 %0, %1, %2;" : "=l"(r) : "l"(a), "l"(b));
    return r;
}

// ---- cluster / DSMEM helpers ----
__device__ __forceinline__ uint32_t smem_u32(const void* p) {
    uint32_t a;
    asm("{ .reg .u64 t; cvta.to.shared.u64 t, %1; cvt.u32.u64 %0, t; }" : "=r"(a) : "l"(p));
    return a;
}
__device__ __forceinline__ uint32_t mapa_u32(uint32_t addr, uint32_t rank) {
    uint32_t r;
    asm("mapa.shared::cluster.u32 %0, %1, %2;" : "=r"(r) : "r"(addr), "r"(rank));
    return r;
}
__device__ __forceinline__ void st_cluster_u64(uint32_t addr, unsigned long long v) {
    asm volatile("st.shared::cluster.u64 [%0], %1;" :: "r"(addr), "l"(v) : "memory");
}
__device__ __forceinline__ unsigned long long ld_vol_u64(uint32_t addr) {
    unsigned long long v;
    asm volatile("ld.volatile.shared.u64 %0, [%1];" : "=l"(v) : "r"(addr) : "memory");
    return v;
}

// ---------------- FPS: 4-CTA cluster per batch ----------------
// R7-proven exchange (in-loop mapa, scalar volatile poll), but each warp's
// lane 0 polls and shfl-broadcasts -> no second __syncthreads per iteration.
__global__ __launch_bounds__(512, 1) __cluster_dims__(CSZ, 1, 1)
void fps_kernel(const float* __restrict__ xyz, float* __restrict__ out) {
    extern __shared__ float dyn[];
    float* sx = dyn;                 // [NPTS] full coord planes
    float* sy = dyn + NPTS;
    float* sz = dyn + 2 * NPTS;
    __shared__ unsigned s_wv[16];
    __shared__ int s_wi[16];
    __shared__ int s_idx[NGRP];
    __shared__ __align__(16) unsigned long long s_box[2][CSZ];

    const int tid  = threadIdx.x;
    const int b    = blockIdx.x >> 2;
    const int rank = blockIdx.x & 3;
    const float* base = xyz + (size_t)b * NPTS * 6;
    const int gbase = rank * PPC;

#pragma unroll
    for (int k = 0; k < 16; k++) {
        int p = tid + (k << 9);
        float x = __ldg(base + p * 6 + 0);
        float y = __ldg(base + p * 6 + 1);
        float z = __ldg(base + p * 6 + 2);
        sx[p] = x; sy[p] = y; sz[p] = z;
        if (p >= gbase && p < gbase + PPC) {
            float xn = __fadd_rn(__fadd_rn(__fmul_rn(x, x), __fmul_rn(y, y)),
                                 __fmul_rn(z, z));
            g_pts[b * NPTS + p] = make_float4(x, y, z, xn);
        }
    }
    if (tid < 2 * CSZ) s_box[tid >> 2][tid & 3] = 0ull;   // tag=0, t starts at 1
    if (tid == 0) s_idx[0] = 0;
    __syncthreads();
    asm volatile("barrier.cluster.arrive.aligned;" ::: "memory");
    asm volatile("barrier.cluster.wait.aligned;" ::: "memory");

    // own points into registers (from smem)
    float tx[4], ty[4], tz[4], pd[4];
#pragma unroll
    for (int k = 0; k < 4; k++) {
        int g = gbase + tid + (k << 9);
        tx[k] = sx[g]; ty[k] = sy[g]; tz[k] = sz[g]; pd[k] = 1e10f;
    }
    unsigned long long px2[2], py2[2], pz2[2];
#pragma unroll
    for (int j = 0; j < 2; j++) {
        px2[j] = f2pack(tx[2 * j], tx[2 * j + 1]);
        py2[j] = f2pack(ty[2 * j], ty[2 * j + 1]);
        pz2[j] = f2pack(tz[2 * j], tz[2 * j + 1]);
    }

    const uint32_t box_a = smem_u32(&s_box[0][0]);
    const int lane = tid & 31, wid = tid >> 5;

    float cx = __ldg(base + 0), cy = __ldg(base + 1), cz = __ldg(base + 2);

    for (int t = 1; t < NGRP; t++) {
        unsigned long long ncx2 = f2pack(-cx, -cx);
        unsigned long long ncy2 = f2pack(-cy, -cy);
        unsigned long long ncz2 = f2pack(-cz, -cz);
        float bv = -1.0f;
        int bi = 0x7FFFFFFF;
#pragma unroll
        for (int j = 0; j < 2; j++) {
            unsigned long long dx = f2add(px2[j], ncx2);   // x + (-c) == x - c exact
            unsigned long long dy = f2add(py2[j], ncy2);
            unsigned long long dz = f2add(pz2[j], ncz2);
            unsigned long long s = f2add(f2add(f2mul(dx, dx), f2mul(dy, dy)),
                                         f2mul(dz, dz));
            float dlo, dhi;
            f2unpack(s, dlo, dhi);
            float n0 = fminf(pd[2 * j], dlo);
            pd[2 * j] = n0;
            if (n0 > bv) { bv = n0; bi = tid + ((2 * j) << 9); }
            float n1 = fminf(pd[2 * j + 1], dhi);
            pd[2 * j + 1] = n1;
            if (n1 > bv) { bv = n1; bi = tid + ((2 * j + 1) << 9); }
        }
        unsigned vb = __float_as_uint(bv);
        unsigned vmax = __reduce_max_sync(0xFFFFFFFFu, vb);
        int cand = (vb == vmax) ? bi : 0x7FFFFFFF;
        int imin = __reduce_min_sync(0xFFFFFFFFu, cand);
        if (lane == 0) { s_wv[wid] = vmax; s_wi[wid] = imin; }
        __syncthreads();

        const int buf = t & 1;
        const unsigned tag = (unsigned)t;
        if (wid == 0) {
            unsigned v2 = (lane < 16) ? s_wv[lane] : 0u;
            unsigned m2 = __reduce_max_sync(0xFFFFFFFFu, v2);
            int c2 = (lane < 16 && v2 == m2) ? s_wi[lane] : 0x7FFFFFFF;
            int lbest = __reduce_min_sync(0xFFFFFFFFu, c2);
            unsigned gidx = (unsigned)(gbase + lbest);
            unsigned long long key = ((unsigned long long)m2 << 32)
                                   | ((unsigned long long)(8191u - gidx) << 19)
                                   | (unsigned long long)tag;
            if (lane < CSZ) {
                uint32_t dst = mapa_u32(box_a + (unsigned)(buf * CSZ + rank) * 8u,
                                        (uint32_t)lane);
                st_cluster_u64(dst, key);   // 4 lanes deliver in parallel
            }
        }
        // each warp: lane 0 polls local box (scalar volatile LDS), shfl-broadcast
        int cur;
        if (lane == 0) {
            const uint32_t pa = box_a + (unsigned)(buf * CSZ) * 8u;
            unsigned long long k0, k1, k2, k3;
            for (;;) {
                k0 = ld_vol_u64(pa);
                k1 = ld_vol_u64(pa + 8u);
                k2 = ld_vol_u64(pa + 16u);
                k3 = ld_vol_u64(pa + 24u);
                if (((unsigned)k0 & TAGM) == tag && ((unsigned)k1 & TAGM) == tag &&
                    ((unsigned)k2 & TAGM) == tag && ((unsigned)k3 & TAGM) == tag)
                    break;
            }
            unsigned long long bk = k0;
            if (k1 > bk) bk = k1;
            if (k2 > bk) bk = k2;
            if (k3 > bk) bk = k3;
            cur = 8191 - (int)((bk >> 19) & 0x1FFFull);
            if (rank == 0 && wid == 0) s_idx[t] = cur;
        }
        cur = __shfl_sync(0xFFFFFFFFu, cur, 0);
        cx = sx[cur]; cy = sy[cur]; cz = sz[cur];
    }
    __syncthreads();   // s_idx writes -> epilogue reads

    if (rank == 0 && tid < NGRP) {
        int idx = s_idx[tid];
        int go = b * NGRP + tid;
        float wx = sx[idx], wy = sy[idx], wz = sz[idx];
        out[CENTER_OFF + go * 3 + 0] = wx;
        out[CENTER_OFF + go * 3 + 1] = wy;
        out[CENTER_OFF + go * 3 + 2] = wz;
        g_center[go * 3 + 0] = wx;
        g_center[go * 3 + 1] = wy;
        g_center[go * 3 + 2] = wz;
        const float* ap = base + idx * 6 + 3;
        out[CATTR_OFF + go * 3 + 0] = __ldg(ap + 0);
        out[CATTR_OFF + go * 3 + 1] = __ldg(ap + 1);
        out[CATTR_OFF + go * 3 + 2] = __ldg(ap + 2);
    }
    asm volatile("barrier.cluster.arrive.aligned;" ::: "memory");
    asm volatile("barrier.cluster.wait.aligned;" ::: "memory");
}

// ---------------- kNN: one CTA (512 threads) per TWO groups ----------------
// Both centers share the same 16 float4 loads per thread. Same fp orders:
// FMA-chain dot (dot_general/BLAS), mul/add norms (XLA fusion).
__global__ __launch_bounds__(512)
void knn_kernel(const float* __restrict__ xyz, float* __restrict__ out) {
    __shared__ float s_c[2][4];
    __shared__ unsigned long long s_min[2][512];
    __shared__ unsigned long long s_src[2][64];
    __shared__ unsigned long long s_T[2];
    __shared__ int s_cnt[2];
    __shared__ unsigned long long s_cand[2][CAP];

    const int tid = threadIdx.x;
    const int pair = blockIdx.x;          // 0..2047
    const int b = pair >> 8;              // 256 pairs per batch
    const int bg0 = b * NGRP + ((pair & 255) << 1);

    if (tid < 2) {
        float cx = g_center[(bg0 + tid) * 3 + 0];
        float cy = g_center[(bg0 + tid) * 3 + 1];
        float cz = g_center[(bg0 + tid) * 3 + 2];
        s_c[tid][0] = cx; s_c[tid][1] = cy; s_c[tid][2] = cz;
        s_c[tid][3] = __fadd_rn(__fadd_rn(__fmul_rn(cx, cx), __fmul_rn(cy, cy)),
                                __fmul_rn(cz, cz));
        s_cnt[tid] = 0;
    }
    __syncthreads();
    const float c0x = s_c[0][0], c0y = s_c[0][1], c0z = s_c[0][2], c0n = s_c[0][3];
    const float c1x = s_c[1][0], c1y = s_c[1][1], c1z = s_c[1][2], c1n = s_c[1][3];
    const float4* __restrict__ pts = g_pts + (size_t)b * NPTS;

    unsigned keys0[16], keys1[16];
    unsigned long long mn0 = ~0ull, mn1 = ~0ull;
#pragma unroll
    for (int k = 0; k < 16; k++) {
        int p = tid + (k << 9);
        float4 q = __ldg(pts + p);
        float dt0 = __fmaf_rn(c0z, q.z, __fmaf_rn(c0y, q.y, __fmul_rn(c0x, q.x)));
        float d20 = __fadd_rn(__fsub_rn(c0n, __fmul_rn(2.0f, dt0)), q.w);
        unsigned u0 = __float_as_uint(d20);
        unsigned key0 = u0 ^ ((unsigned)((int)u0 >> 31) | 0x80000000u);
        keys0[k] = key0;
        unsigned long long pk0 = ((unsigned long long)key0 << 32) | (unsigned)p;
        if (pk0 < mn0) mn0 = pk0;

        float dt1 = __fmaf_rn(c1z, q.z, __fmaf_rn(c1y, q.y, __fmul_rn(c1x, q.x)));
        float d21 = __fadd_rn(__fsub_rn(c1n, __fmul_rn(2.0f, dt1)), q.w);
        unsigned u1 = __float_as_uint(d21);
        unsigned key1 = u1 ^ ((unsigned)((int)u1 >> 31) | 0x80000000u);
        keys1[k] = key1;
        unsigned long long pk1 = ((unsigned long long)key1 << 32) | (unsigned)p;
        if (pk1 < mn1) mn1 = pk1;
    }
    s_min[0][tid] = mn0;
    s_min[1][tid] = mn1;
    __syncthreads();

    if (tid < 128) {
        int grp = tid >> 6, i = tid & 63;
        unsigned long long a = s_min[grp][8 * i];
#pragma unroll
        for (int j = 1; j < 8; j++) {
            unsigned long long v = s_min[grp][8 * i + j];
            if (v < a) a = v;
        }
        s_src[grp][i] = a;
    }
    __syncthreads();
    if (tid < 128) {
        int grp = tid >> 6, i = tid & 63;
        unsigned long long m = s_src[grp][i];
        int r = 0;
        for (int j = 0; j < 64; j++) r += (s_src[grp][j] < m) ? 1 : 0;
        if (r == 31) s_T[grp] = m;   // keys unique -> exactly one writer per group
    }
    __syncthreads();
    const unsigned long long T0 = s_T[0], T1 = s_T[1];

#pragma unroll
    for (int k = 0; k < 16; k++) {
        unsigned p = (unsigned)(tid + (k << 9));
        unsigned long long pk0 = ((unsigned long long)keys0[k] << 32) | p;
        if (pk0 <= T0) {
            int pos = atomicAdd(&s_cnt[0], 1);
            if (pos < CAP) s_cand[0][pos] = pk0;
        }
        unsigned long long pk1 = ((unsigned long long)keys1[k] << 32) | p;
        if (pk1 <= T1) {
            int pos = atomicAdd(&s_cnt[1], 1);
            if (pos < CAP) s_cand[1][pos] = pk1;
        }
    }
    __syncthreads();

    {
        int grp = tid >> 8;           // threads 0-255 -> grp0, 256-511 -> grp1
        int lt = tid & 255;
        int n = s_cnt[grp];
        if (n > CAP) n = CAP;
        int bg = bg0 + grp;
        float cx = s_c[grp][0], cy = s_c[grp][1], cz = s_c[grp][2];
        for (int c = lt; c < n; c += 256) {
            unsigned long long pk = s_cand[grp][c];
            int r = 0;
            for (int j = 0; j < n; j++) r += (s_cand[grp][j] < pk) ? 1 : 0;
            if (r < KNN) {
                int p = (int)(pk & 0xFFFFFFFFull);
                const float* pp = xyz + ((size_t)b * NPTS + p) * 6;
                size_t o = ((size_t)bg * KNN + r) * 3;
                out[o + 0] = __fsub_rn(__ldg(pp + 0), cx);
                out[o + 1] = __fsub_rn(__ldg(pp + 1), cy);
                out[o + 2] = __fsub_rn(__ldg(pp + 2), cz);
                out[NEIGH_ATTR_OFF + o + 0] = __ldg(pp + 3);
                out[NEIGH_ATTR_OFF + o + 1] = __ldg(pp + 4);
                out[NEIGH_ATTR_OFF + o + 2] = __ldg(pp + 5);
            }
        }
    }
}

extern "C" void kernel_launch(void* const* d_in, const int* in_sizes, int n_in,
                              void* d_out, int out_size) {
    const float* xyz = (const float*)d_in[0];
    float* out = (float*)d_out;
    (void)in_sizes; (void)n_in; (void)out_size;

    const int smem = 3 * NPTS * (int)sizeof(float);   // 96 KB coord planes
    cudaFuncSetAttribute(fps_kernel, cudaFuncAttributeMaxDynamicSharedMemorySize, smem);
    fps_kernel<<<BATCH * CSZ, 512, smem>>>(xyz, out);
    knn_kernel<<<BATCH * NGRP / 2, 512>>>(xyz, out);
}